// round 11
// baseline (speedup 1.0000x reference)
#include <cuda_runtime.h>
#include <math.h>

#define MAXB 32768

__device__ float  g_pooled[MAXB * 64];   // [B][4 features * 16 dims]
__device__ float  g_part[256 * 128];     // per-block stat partials
__device__ float  g_mu[64];
__device__ float  g_var[64];
__device__ float4 g_W1t4[64 * 28];       // W1 transposed [j][i], filled by bn_kernel

__device__ __forceinline__ float fm(float a, float b) { return __fmul_rn(a, b); }
__device__ __forceinline__ float fa(float a, float b) { return __fadd_rn(a, b); }

// ---------------------------------------------------------------------------
// Pooling: blockIdx.y = feature (warp-uniform). Grid x sized for 4 thr/row.
//   f0 ('sum',   genre): 1 thread/row, genre table in smem.
//   f1 ('atten', movie): 4 threads/row; each lane computes exp/id for its
//        pos%4 slice only; den/num chains rebuilt in exact pos-order from
//        shuffled values (bit-identical: same operands, same op order).
//   f2 ('max',   genre): 1 thread/row, per-id L2 precomputed in smem.
//   f3 ('korder', tag):  4 threads/row; n2 rebuilt bit-exactly per lane.
// ---------------------------------------------------------------------------
__global__ __launch_bounds__(128) void pool8_kernel(
    const int* __restrict__ ug, const int* __restrict__ urbv,
    const int* __restrict__ mg, const int* __restrict__ mt,
    const int* __restrict__ ug_c, const int* __restrict__ urb_c,
    const int* __restrict__ mg_c, const int* __restrict__ mt_c,
    const float* __restrict__ emb_movie, const float* __restrict__ emb_tag,
    const float* __restrict__ emb_genre, const float* __restrict__ at_movie,
    int B)
{
    __shared__ float4 s_gen[30 * 4];
    __shared__ float  s_l2[30];
    int tid = threadIdx.x;
    int feat = blockIdx.y;

    if (feat == 0 || feat == 2) {
        if (tid < 120) s_gen[tid] = reinterpret_cast<const float4*>(emb_genre)[tid];
        __syncthreads();
        if (feat == 2) {
            if (tid < 30) {
                float4 e0 = s_gen[tid*4], e1 = s_gen[tid*4+1],
                       e2 = s_gen[tid*4+2], e3 = s_gen[tid*4+3];
                float l2 = 0.f;
                l2=fa(l2,fm(e0.x,e0.x)); l2=fa(l2,fm(e0.y,e0.y)); l2=fa(l2,fm(e0.z,e0.z)); l2=fa(l2,fm(e0.w,e0.w));
                l2=fa(l2,fm(e1.x,e1.x)); l2=fa(l2,fm(e1.y,e1.y)); l2=fa(l2,fm(e1.z,e1.z)); l2=fa(l2,fm(e1.w,e1.w));
                l2=fa(l2,fm(e2.x,e2.x)); l2=fa(l2,fm(e2.y,e2.y)); l2=fa(l2,fm(e2.z,e2.z)); l2=fa(l2,fm(e2.w,e2.w));
                l2=fa(l2,fm(e3.x,e3.x)); l2=fa(l2,fm(e3.y,e3.y)); l2=fa(l2,fm(e3.z,e3.z)); l2=fa(l2,fm(e3.w,e3.w));
                s_l2[tid] = l2;
            }
            __syncthreads();
        }
    }

    int gtid = blockIdx.x * 128 + tid;
    int lane = tid & 31;
    const float4* mov4 = reinterpret_cast<const float4*>(emb_movie);
    const float4* tag4 = reinterpret_cast<const float4*>(emb_tag);

    if (feat == 0) {
        int row = gtid;
        if (row >= B) return;
        float4* outp = reinterpret_cast<float4*>(g_pooled + row * 64);
        int cnt = ug_c[row];
        const int* idp = ug + row * 50;
        float4 p0 = {0,0,0,0}, p1 = {0,0,0,0}, p2 = {0,0,0,0}, p3 = {0,0,0,0};
        for (int pos = 0; pos < cnt; pos++) {
            int id = idp[pos] * 4;
            float4 e0 = s_gen[id], e1 = s_gen[id+1], e2 = s_gen[id+2], e3 = s_gen[id+3];
            p0.x=fa(p0.x,e0.x); p0.y=fa(p0.y,e0.y); p0.z=fa(p0.z,e0.z); p0.w=fa(p0.w,e0.w);
            p1.x=fa(p1.x,e1.x); p1.y=fa(p1.y,e1.y); p1.z=fa(p1.z,e1.z); p1.w=fa(p1.w,e1.w);
            p2.x=fa(p2.x,e2.x); p2.y=fa(p2.y,e2.y); p2.z=fa(p2.z,e2.z); p2.w=fa(p2.w,e2.w);
            p3.x=fa(p3.x,e3.x); p3.y=fa(p3.y,e3.y); p3.z=fa(p3.z,e3.z); p3.w=fa(p3.w,e3.w);
        }
        outp[0]=p0; outp[1]=p1; outp[2]=p2; outp[3]=p3;
    } else if (feat == 1) {
        int row = gtid >> 2, c = gtid & 3;
        if (row >= B) return;
        unsigned qm = 0xFu << (lane & 28);
        int qb = lane & 28;
        float4* outp = reinterpret_cast<float4*>(g_pooled + row * 64);
        int cnt = urb_c[row];
        const int* idp = urbv + row * 50;
        // lane-local slices: positions 4k + c
        int   id_loc[13];
        float e_loc[13];
        float M = (cnt < 50) ? 0.f : -1e30f;
        #pragma unroll
        for (int k = 0; k < 13; k++) {
            int pos = k * 4 + c;
            if (pos < cnt) {
                int id = idp[pos];
                id_loc[k] = id;
                float a = at_movie[id];
                e_loc[k] = a;                 // holds av until exp pass
                M = fmaxf(M, a);
            }
        }
        // exact max (fmaxf is associative+commutative): combine across quad
        M = fmaxf(M, __shfl_xor_sync(qm, M, 1));
        M = fmaxf(M, __shfl_xor_sync(qm, M, 2));
        #pragma unroll
        for (int k = 0; k < 13; k++) {
            int pos = k * 4 + c;
            if (pos < cnt) e_loc[k] = expf(__fadd_rn(e_loc[k], -M));
        }
        // den: identical chain in every lane, pos ascending
        float den = fm((float)(50 - cnt), expf(-M));
        #pragma unroll
        for (int k = 0; k < 13; k++) {
            if (k * 4 < cnt) {
                #pragma unroll
                for (int c2 = 0; c2 < 4; c2++) {
                    float e = __shfl_sync(qm, e_loc[k], qb + c2);
                    if (k * 4 + c2 < cnt) den = fa(den, e);
                }
            }
        }
        float invden = __fdiv_rn(1.f, den);
        // num: per-dim chain in pos order; wv identical bits in every lane
        float4 n0 = {0,0,0,0};
        #pragma unroll
        for (int k = 0; k < 13; k++) {
            if (k * 4 < cnt) {
                #pragma unroll
                for (int c2 = 0; c2 < 4; c2++) {
                    if (k * 4 + c2 < cnt) {
                        int   id = __shfl_sync(qm, id_loc[k], qb + c2);
                        float wv = fm(__shfl_sync(qm, e_loc[k], qb + c2), invden);
                        float4 e4 = mov4[id * 4 + c];
                        n0.x = fa(n0.x, fm(e4.x, wv));
                        n0.y = fa(n0.y, fm(e4.y, wv));
                        n0.z = fa(n0.z, fm(e4.z, wv));
                        n0.w = fa(n0.w, fm(e4.w, wv));
                    }
                }
            }
        }
        outp[4 + c] = n0;
    } else if (feat == 2) {
        int row = gtid;
        if (row >= B) return;
        float4* outp = reinterpret_cast<float4*>(g_pooled + row * 64);
        int cnt = mg_c[row];
        const int* idp = mg + row * 50;
        int bidx = -1;
        float best = 0.f;
        for (int pos = 0; pos < cnt; pos++) {
            float l2 = s_l2[idp[pos]];
            if (l2 > best) { best = l2; bidx = pos; }
        }
        if (bidx >= 0) {
            int b = idp[bidx] * 4;
            outp[8] = s_gen[b]; outp[9] = s_gen[b+1]; outp[10] = s_gen[b+2]; outp[11] = s_gen[b+3];
        } else {
            float4 z = {0,0,0,0};
            outp[8] = z; outp[9] = z; outp[10] = z; outp[11] = z;
        }
    } else {
        int row = gtid >> 2, c = gtid & 3;
        if (row >= B) return;
        unsigned qm = 0xFu << (lane & 28);
        int qbase = lane & 28;
        float4* outp = reinterpret_cast<float4*>(g_pooled + row * 64);
        int cnt = mt_c[row];
        const int* idp = mt + row * 50;
        float4 s0 = {0,0,0,0}, q0 = {0,0,0,0};
        for (int pos = 0; pos < cnt; pos++) {
            float4 e0 = tag4[idp[pos] * 4 + c];
            s0.x=fa(s0.x,e0.x); q0.x=fa(q0.x,fm(e0.x,e0.x));
            s0.y=fa(s0.y,e0.y); q0.y=fa(q0.y,fm(e0.y,e0.y));
            s0.z=fa(s0.z,e0.z); q0.z=fa(q0.z,fm(e0.z,e0.z));
            s0.w=fa(s0.w,e0.w); q0.w=fa(q0.w,fm(e0.w,e0.w));
        }
        float4 v0;
        v0.x=fm(0.5f,__fadd_rn(fm(s0.x,s0.x),-q0.x)); v0.y=fm(0.5f,__fadd_rn(fm(s0.y,s0.y),-q0.y));
        v0.z=fm(0.5f,__fadd_rn(fm(s0.z,s0.z),-q0.z)); v0.w=fm(0.5f,__fadd_rn(fm(s0.w,s0.w),-q0.w));
        float w[16];
        #pragma unroll
        for (int qq = 0; qq < 4; qq++) {
            w[qq*4+0] = __shfl_sync(qm, v0.x, qbase + qq);
            w[qq*4+1] = __shfl_sync(qm, v0.y, qbase + qq);
            w[qq*4+2] = __shfl_sync(qm, v0.z, qbase + qq);
            w[qq*4+3] = __shfl_sync(qm, v0.w, qbase + qq);
        }
        float n2 = 0.f;
        #pragma unroll
        for (int d = 0; d < 16; d++) n2 = fa(n2, fm(w[d], w[d]));
        float n = fmaxf(__fsqrt_rn(n2), 1e-12f);
        float invn = __fdiv_rn(1.f, n);
        v0.x=fm(v0.x,invn); v0.y=fm(v0.y,invn); v0.z=fm(v0.z,invn); v0.w=fm(v0.w,invn);
        outp[12 + c] = v0;
    }
}

// ---------------------------------------------------------------------------
__global__ void stats_kernel(int B) {
    int d = threadIdx.x;           // 0..63
    float s = 0.f, q = 0.f;
    for (int r = blockIdx.x; r < B; r += 256) {
        float v = g_pooled[r * 64 + d];
        s = fa(s, v);
        q = fa(q, fm(v, v));
    }
    g_part[blockIdx.x * 128 + d] = s;
    g_part[blockIdx.x * 128 + 64 + d] = q;
}

// Finalize BN stats AND pre-transpose W1.
__global__ void bn_kernel(const float* __restrict__ W1, int B) {
    int t = threadIdx.x;
    if (t < 64) {
        float s = 0.f, q = 0.f;
        for (int b = 0; b < 256; b++) {
            s = fa(s, g_part[b * 128 + t]);
            q = fa(q, g_part[b * 128 + 64 + t]);
        }
        float invB = 1.f / (float)B;
        float mean = s * invB;
        float var  = q * invB - mean * mean;
        g_mu[t] = mean;
        g_var[t] = var;
    }
    float* w1t = reinterpret_cast<float*>(g_W1t4);
    for (int idx = t; idx < 64 * 112; idx += 128) {
        int j = idx / 112, i = idx % 112;
        w1t[j * 112 + i] = W1[i * 64 + j];
    }
}

// ---------------------------------------------------------------------------
// MLP: 4 threads per row (lane c owns input float4s [7c, 7c+7)); each block
// loops over 4 row-tiles so weight staging amortizes over 128 rows.
// ---------------------------------------------------------------------------
__global__ __launch_bounds__(128, 6) void mlp4_kernel(
    const int* __restrict__ uid, const int* __restrict__ mid,
    const int* __restrict__ yr,
    const float* __restrict__ emb_user, const float* __restrict__ emb_movie,
    const float* __restrict__ emb_year,
    const float* __restrict__ gamma, const float* __restrict__ beta,
    const float* __restrict__ b1,
    const float* __restrict__ W2, const float* __restrict__ b2,
    const float* __restrict__ W3, const float* __restrict__ b3,
    float* __restrict__ out, int B)
{
    __shared__ float4 sW1t[64 * 28];   // [j][i/4]
    __shared__ float4 sW2[64 * 8];
    __shared__ float  sb1[64], sMu[64], sR[64], sG[64], sBt[64];
    __shared__ float4 sb2[8], sW3[8];
    __shared__ float  sb3;
    int tid = threadIdx.x;
    #pragma unroll
    for (int k = 0; k < 14; k++)
        sW1t[tid + 128 * k] = g_W1t4[tid + 128 * k];
    for (int idx = tid; idx < 64 * 8; idx += 128)
        sW2[idx] = reinterpret_cast<const float4*>(W2)[idx];
    if (tid < 64) {
        sb1[tid] = b1[tid];
        sMu[tid] = g_mu[tid];
        sR[tid]  = rsqrtf(__fadd_rn(g_var[tid], 1e-5f));
        sG[tid]  = gamma[tid];
        sBt[tid] = beta[tid];
    }
    if (tid < 8) {
        sb2[tid] = reinterpret_cast<const float4*>(b2)[tid];
        sW3[tid] = reinterpret_cast<const float4*>(W3)[tid];
    }
    if (tid == 0) sb3 = b3[0];
    __syncthreads();

    int c = tid & 3;
    unsigned qm = 0xFu << ((tid & 31) & 28);

    #pragma unroll 1
    for (int it = 0; it < 4; it++) {
        int row = blockIdx.x * 128 + it * 32 + (tid >> 2);
        if (row >= B) continue;

        const float4* pu  = reinterpret_cast<const float4*>(emb_user)  + uid[row] * 4;
        const float4* pmv = reinterpret_cast<const float4*>(emb_movie) + mid[row] * 4;
        const float4* py  = reinterpret_cast<const float4*>(emb_year)  + yr[row] * 4;
        const float4* pp  = reinterpret_cast<const float4*>(g_pooled + row * 64);

        float x[28];
        #pragma unroll
        for (int qq = 0; qq < 7; qq++) {
            int q = c * 7 + qq;
            float4 v;
            if (q < 4)        v = pu[q];
            else if (q < 8)   v = pmv[q - 4];
            else if (q < 12)  v = py[q - 8];
            else {
                v = pp[q - 12];
                int t0 = (q - 12) * 4;
                v.x = fa(fm(fm(__fadd_rn(v.x, -sMu[t0+0]), sR[t0+0]), sG[t0+0]), sBt[t0+0]);
                v.y = fa(fm(fm(__fadd_rn(v.y, -sMu[t0+1]), sR[t0+1]), sG[t0+1]), sBt[t0+1]);
                v.z = fa(fm(fm(__fadd_rn(v.z, -sMu[t0+2]), sR[t0+2]), sG[t0+2]), sBt[t0+2]);
                v.w = fa(fm(fm(__fadd_rn(v.w, -sMu[t0+3]), sR[t0+3]), sG[t0+3]), sBt[t0+3]);
            }
            x[qq*4+0]=v.x; x[qq*4+1]=v.y; x[qq*4+2]=v.z; x[qq*4+3]=v.w;
        }

        float4 acc0 = sb2[c * 2], acc1 = sb2[c * 2 + 1];

        #pragma unroll 4
        for (int j = 0; j < 64; j++) {
            float t0 = 0.f, t1 = 0.f, t2 = 0.f, t3 = 0.f;
            const float4* wrow = sW1t + j * 28 + c * 7;
            #pragma unroll
            for (int ii = 0; ii < 7; ii++) {
                float4 w = wrow[ii];
                t0 = fmaf(x[ii*4+0], w.x, t0);
                t1 = fmaf(x[ii*4+1], w.y, t1);
                t2 = fmaf(x[ii*4+2], w.z, t2);
                t3 = fmaf(x[ii*4+3], w.w, t3);
            }
            float s = (t0 + t1) + (t2 + t3);
            s = fa(s, __shfl_xor_sync(qm, s, 1));   // commutative fadd:
            s = fa(s, __shfl_xor_sync(qm, s, 2));   // identical bits all lanes
            float t = fmaxf(sb1[j] + s, 0.f);
            const float4* w2row = sW2 + j * 8 + c * 2;
            float4 w20 = w2row[0], w21 = w2row[1];
            acc0.x = fmaf(t, w20.x, acc0.x); acc0.y = fmaf(t, w20.y, acc0.y);
            acc0.z = fmaf(t, w20.z, acc0.z); acc0.w = fmaf(t, w20.w, acc0.w);
            acc1.x = fmaf(t, w21.x, acc1.x); acc1.y = fmaf(t, w21.y, acc1.y);
            acc1.z = fmaf(t, w21.z, acc1.z); acc1.w = fmaf(t, w21.w, acc1.w);
        }

        float4 w30 = sW3[c * 2], w31 = sW3[c * 2 + 1];
        float zh = fmaxf(acc0.x, 0.f) * w30.x + fmaxf(acc0.y, 0.f) * w30.y
                 + fmaxf(acc0.z, 0.f) * w30.z + fmaxf(acc0.w, 0.f) * w30.w
                 + fmaxf(acc1.x, 0.f) * w31.x + fmaxf(acc1.y, 0.f) * w31.y
                 + fmaxf(acc1.z, 0.f) * w31.z + fmaxf(acc1.w, 0.f) * w31.w;
        zh = fa(zh, __shfl_xor_sync(qm, zh, 1));
        zh = fa(zh, __shfl_xor_sync(qm, zh, 2));
        if (c == 0) {
            float z = sb3 + zh;
            out[row] = 1.f / (1.f + expf(-z));
        }
    }
}

// ---------------------------------------------------------------------------
extern "C" void kernel_launch(void* const* d_in, const int* in_sizes, int n_in,
                              void* d_out, int out_size)
{
    const int* user_id  = (const int*)d_in[0];
    const int* movie_id = (const int*)d_in[1];
    const int* year     = (const int*)d_in[2];
    const int* ug       = (const int*)d_in[3];
    const int* urbv     = (const int*)d_in[4];
    const int* mg       = (const int*)d_in[5];
    const int* mt       = (const int*)d_in[6];
    const int* ug_c     = (const int*)d_in[7];
    const int* urb_c    = (const int*)d_in[8];
    const int* mg_c     = (const int*)d_in[9];
    const int* mt_c     = (const int*)d_in[10];
    const float* emb_user  = (const float*)d_in[11];
    const float* emb_movie = (const float*)d_in[12];
    const float* emb_tag   = (const float*)d_in[13];
    const float* emb_genre = (const float*)d_in[14];
    const float* emb_year  = (const float*)d_in[15];
    const float* at_movie  = (const float*)d_in[16];
    // d_in[17] = at_tagId   (unused by korder)
    // d_in[18] = at_genreId (unused by sum/max)
    const float* gamma = (const float*)d_in[19];
    const float* beta  = (const float*)d_in[20];
    const float* W1 = (const float*)d_in[21];
    const float* b1 = (const float*)d_in[22];
    const float* W2 = (const float*)d_in[23];
    const float* b2 = (const float*)d_in[24];
    const float* W3 = (const float*)d_in[25];
    const float* b3 = (const float*)d_in[26];
    int B = in_sizes[0];

    dim3 pgrid((4 * B + 127) / 128, 4);   // f1/f3 use 4 threads/row
    pool8_kernel<<<pgrid, 128>>>(
        ug, urbv, mg, mt, ug_c, urb_c, mg_c, mt_c,
        emb_movie, emb_tag, emb_genre, at_movie, B);
    stats_kernel<<<256, 64>>>(B);
    bn_kernel<<<1, 128>>>(W1, B);
    mlp4_kernel<<<(B + 127) / 128, 128>>>(
        user_id, movie_id, year, emb_user, emb_movie, emb_year,
        gamma, beta, b1, W2, b2, W3, b3, (float*)d_out, B);
}

// round 12
// speedup vs baseline: 1.2655x; 1.2655x over previous
#include <cuda_runtime.h>
#include <math.h>

#define MAXB 32768

__device__ float  g_pooled[MAXB * 64];   // [B][4 features * 16 dims]
__device__ float  g_part[256 * 128];     // per-block stat partials
__device__ float  g_mu[64];
__device__ float  g_var[64];
__device__ float4 g_W1t4[64 * 28];       // W1 transposed [j][i], filled by bn_kernel

__device__ __forceinline__ float fm(float a, float b) { return __fmul_rn(a, b); }
__device__ __forceinline__ float fa(float a, float b) { return __fadd_rn(a, b); }

// ---------------------------------------------------------------------------
// Pooling (unchanged from R11 pass): blockIdx.y = feature.
// ---------------------------------------------------------------------------
__global__ __launch_bounds__(128) void pool8_kernel(
    const int* __restrict__ ug, const int* __restrict__ urbv,
    const int* __restrict__ mg, const int* __restrict__ mt,
    const int* __restrict__ ug_c, const int* __restrict__ urb_c,
    const int* __restrict__ mg_c, const int* __restrict__ mt_c,
    const float* __restrict__ emb_movie, const float* __restrict__ emb_tag,
    const float* __restrict__ emb_genre, const float* __restrict__ at_movie,
    int B)
{
    __shared__ float4 s_gen[30 * 4];
    __shared__ float  s_l2[30];
    int tid = threadIdx.x;
    int feat = blockIdx.y;

    if (feat == 0 || feat == 2) {
        if (tid < 120) s_gen[tid] = reinterpret_cast<const float4*>(emb_genre)[tid];
        __syncthreads();
        if (feat == 2) {
            if (tid < 30) {
                float4 e0 = s_gen[tid*4], e1 = s_gen[tid*4+1],
                       e2 = s_gen[tid*4+2], e3 = s_gen[tid*4+3];
                float l2 = 0.f;
                l2=fa(l2,fm(e0.x,e0.x)); l2=fa(l2,fm(e0.y,e0.y)); l2=fa(l2,fm(e0.z,e0.z)); l2=fa(l2,fm(e0.w,e0.w));
                l2=fa(l2,fm(e1.x,e1.x)); l2=fa(l2,fm(e1.y,e1.y)); l2=fa(l2,fm(e1.z,e1.z)); l2=fa(l2,fm(e1.w,e1.w));
                l2=fa(l2,fm(e2.x,e2.x)); l2=fa(l2,fm(e2.y,e2.y)); l2=fa(l2,fm(e2.z,e2.z)); l2=fa(l2,fm(e2.w,e2.w));
                l2=fa(l2,fm(e3.x,e3.x)); l2=fa(l2,fm(e3.y,e3.y)); l2=fa(l2,fm(e3.z,e3.z)); l2=fa(l2,fm(e3.w,e3.w));
                s_l2[tid] = l2;
            }
            __syncthreads();
        }
    }

    int gtid = blockIdx.x * 128 + tid;
    int lane = tid & 31;
    const float4* mov4 = reinterpret_cast<const float4*>(emb_movie);
    const float4* tag4 = reinterpret_cast<const float4*>(emb_tag);

    if (feat == 0) {
        int row = gtid;
        if (row >= B) return;
        float4* outp = reinterpret_cast<float4*>(g_pooled + row * 64);
        int cnt = ug_c[row];
        const int* idp = ug + row * 50;
        float4 p0 = {0,0,0,0}, p1 = {0,0,0,0}, p2 = {0,0,0,0}, p3 = {0,0,0,0};
        for (int pos = 0; pos < cnt; pos++) {
            int id = idp[pos] * 4;
            float4 e0 = s_gen[id], e1 = s_gen[id+1], e2 = s_gen[id+2], e3 = s_gen[id+3];
            p0.x=fa(p0.x,e0.x); p0.y=fa(p0.y,e0.y); p0.z=fa(p0.z,e0.z); p0.w=fa(p0.w,e0.w);
            p1.x=fa(p1.x,e1.x); p1.y=fa(p1.y,e1.y); p1.z=fa(p1.z,e1.z); p1.w=fa(p1.w,e1.w);
            p2.x=fa(p2.x,e2.x); p2.y=fa(p2.y,e2.y); p2.z=fa(p2.z,e2.z); p2.w=fa(p2.w,e2.w);
            p3.x=fa(p3.x,e3.x); p3.y=fa(p3.y,e3.y); p3.z=fa(p3.z,e3.z); p3.w=fa(p3.w,e3.w);
        }
        outp[0]=p0; outp[1]=p1; outp[2]=p2; outp[3]=p3;
    } else if (feat == 1) {
        int row = gtid >> 2, c = gtid & 3;
        if (row >= B) return;
        unsigned qm = 0xFu << (lane & 28);
        int qb = lane & 28;
        float4* outp = reinterpret_cast<float4*>(g_pooled + row * 64);
        int cnt = urb_c[row];
        const int* idp = urbv + row * 50;
        int   id_loc[13];
        float e_loc[13];
        float M = (cnt < 50) ? 0.f : -1e30f;
        #pragma unroll
        for (int k = 0; k < 13; k++) {
            int pos = k * 4 + c;
            if (pos < cnt) {
                int id = idp[pos];
                id_loc[k] = id;
                float a = at_movie[id];
                e_loc[k] = a;
                M = fmaxf(M, a);
            }
        }
        M = fmaxf(M, __shfl_xor_sync(qm, M, 1));
        M = fmaxf(M, __shfl_xor_sync(qm, M, 2));
        #pragma unroll
        for (int k = 0; k < 13; k++) {
            int pos = k * 4 + c;
            if (pos < cnt) e_loc[k] = expf(__fadd_rn(e_loc[k], -M));
        }
        float den = fm((float)(50 - cnt), expf(-M));
        #pragma unroll
        for (int k = 0; k < 13; k++) {
            if (k * 4 < cnt) {
                #pragma unroll
                for (int c2 = 0; c2 < 4; c2++) {
                    float e = __shfl_sync(qm, e_loc[k], qb + c2);
                    if (k * 4 + c2 < cnt) den = fa(den, e);
                }
            }
        }
        float invden = __fdiv_rn(1.f, den);
        float4 n0 = {0,0,0,0};
        #pragma unroll
        for (int k = 0; k < 13; k++) {
            if (k * 4 < cnt) {
                #pragma unroll
                for (int c2 = 0; c2 < 4; c2++) {
                    if (k * 4 + c2 < cnt) {
                        int   id = __shfl_sync(qm, id_loc[k], qb + c2);
                        float wv = fm(__shfl_sync(qm, e_loc[k], qb + c2), invden);
                        float4 e4 = mov4[id * 4 + c];
                        n0.x = fa(n0.x, fm(e4.x, wv));
                        n0.y = fa(n0.y, fm(e4.y, wv));
                        n0.z = fa(n0.z, fm(e4.z, wv));
                        n0.w = fa(n0.w, fm(e4.w, wv));
                    }
                }
            }
        }
        outp[4 + c] = n0;
    } else if (feat == 2) {
        int row = gtid;
        if (row >= B) return;
        float4* outp = reinterpret_cast<float4*>(g_pooled + row * 64);
        int cnt = mg_c[row];
        const int* idp = mg + row * 50;
        int bidx = -1;
        float best = 0.f;
        for (int pos = 0; pos < cnt; pos++) {
            float l2 = s_l2[idp[pos]];
            if (l2 > best) { best = l2; bidx = pos; }
        }
        if (bidx >= 0) {
            int b = idp[bidx] * 4;
            outp[8] = s_gen[b]; outp[9] = s_gen[b+1]; outp[10] = s_gen[b+2]; outp[11] = s_gen[b+3];
        } else {
            float4 z = {0,0,0,0};
            outp[8] = z; outp[9] = z; outp[10] = z; outp[11] = z;
        }
    } else {
        int row = gtid >> 2, c = gtid & 3;
        if (row >= B) return;
        unsigned qm = 0xFu << (lane & 28);
        int qbase = lane & 28;
        float4* outp = reinterpret_cast<float4*>(g_pooled + row * 64);
        int cnt = mt_c[row];
        const int* idp = mt + row * 50;
        float4 s0 = {0,0,0,0}, q0 = {0,0,0,0};
        for (int pos = 0; pos < cnt; pos++) {
            float4 e0 = tag4[idp[pos] * 4 + c];
            s0.x=fa(s0.x,e0.x); q0.x=fa(q0.x,fm(e0.x,e0.x));
            s0.y=fa(s0.y,e0.y); q0.y=fa(q0.y,fm(e0.y,e0.y));
            s0.z=fa(s0.z,e0.z); q0.z=fa(q0.z,fm(e0.z,e0.z));
            s0.w=fa(s0.w,e0.w); q0.w=fa(q0.w,fm(e0.w,e0.w));
        }
        float4 v0;
        v0.x=fm(0.5f,__fadd_rn(fm(s0.x,s0.x),-q0.x)); v0.y=fm(0.5f,__fadd_rn(fm(s0.y,s0.y),-q0.y));
        v0.z=fm(0.5f,__fadd_rn(fm(s0.z,s0.z),-q0.z)); v0.w=fm(0.5f,__fadd_rn(fm(s0.w,s0.w),-q0.w));
        float w[16];
        #pragma unroll
        for (int qq = 0; qq < 4; qq++) {
            w[qq*4+0] = __shfl_sync(qm, v0.x, qbase + qq);
            w[qq*4+1] = __shfl_sync(qm, v0.y, qbase + qq);
            w[qq*4+2] = __shfl_sync(qm, v0.z, qbase + qq);
            w[qq*4+3] = __shfl_sync(qm, v0.w, qbase + qq);
        }
        float n2 = 0.f;
        #pragma unroll
        for (int d = 0; d < 16; d++) n2 = fa(n2, fm(w[d], w[d]));
        float n = fmaxf(__fsqrt_rn(n2), 1e-12f);
        float invn = __fdiv_rn(1.f, n);
        v0.x=fm(v0.x,invn); v0.y=fm(v0.y,invn); v0.z=fm(v0.z,invn); v0.w=fm(v0.w,invn);
        outp[12 + c] = v0;
    }
}

// ---------------------------------------------------------------------------
__global__ void stats_kernel(int B) {
    int d = threadIdx.x;           // 0..63
    float s = 0.f, q = 0.f;
    for (int r = blockIdx.x; r < B; r += 256) {
        float v = g_pooled[r * 64 + d];
        s = fa(s, v);
        q = fa(q, fm(v, v));
    }
    g_part[blockIdx.x * 128 + d] = s;
    g_part[blockIdx.x * 128 + 64 + d] = q;
}

// Finalize BN stats AND pre-transpose W1.
__global__ void bn_kernel(const float* __restrict__ W1, int B) {
    int t = threadIdx.x;
    if (t < 64) {
        float s = 0.f, q = 0.f;
        for (int b = 0; b < 256; b++) {
            s = fa(s, g_part[b * 128 + t]);
            q = fa(q, g_part[b * 128 + 64 + t]);
        }
        float invB = 1.f / (float)B;
        float mean = s * invB;
        float var  = q * invB - mean * mean;
        g_mu[t] = mean;
        g_var[t] = var;
    }
    float* w1t = reinterpret_cast<float*>(g_W1t4);
    for (int idx = t; idx < 64 * 112; idx += 128) {
        int j = idx / 112, i = idx % 112;
        w1t[j * 112 + i] = W1[i * 64 + j];
    }
}

// ---------------------------------------------------------------------------
// MLP (exact R10 mlp3: 2 threads/row, grid = 2B/128, 35.1us measured).
// ---------------------------------------------------------------------------
__global__ __launch_bounds__(128, 4) void mlp3_kernel(
    const int* __restrict__ uid, const int* __restrict__ mid,
    const int* __restrict__ yr,
    const float* __restrict__ emb_user, const float* __restrict__ emb_movie,
    const float* __restrict__ emb_year,
    const float* __restrict__ gamma, const float* __restrict__ beta,
    const float* __restrict__ b1,
    const float* __restrict__ W2, const float* __restrict__ b2,
    const float* __restrict__ W3, const float* __restrict__ b3,
    float* __restrict__ out, int B)
{
    __shared__ float4 sW1t[64 * 28];   // [j][i/4]
    __shared__ float4 sW2[64 * 8];
    __shared__ float  sb1[64], sMu[64], sR[64], sG[64], sBt[64];
    __shared__ float4 sb2[8], sW3[8];
    __shared__ float  sb3;
    int tid = threadIdx.x;
    #pragma unroll
    for (int k = 0; k < 14; k++)
        sW1t[tid + 128 * k] = g_W1t4[tid + 128 * k];
    for (int idx = tid; idx < 64 * 8; idx += 128)
        sW2[idx] = reinterpret_cast<const float4*>(W2)[idx];
    if (tid < 64) {
        sb1[tid] = b1[tid];
        sMu[tid] = g_mu[tid];
        sR[tid]  = rsqrtf(__fadd_rn(g_var[tid], 1e-5f));
        sG[tid]  = gamma[tid];
        sBt[tid] = beta[tid];
    }
    if (tid < 8) {
        sb2[tid] = reinterpret_cast<const float4*>(b2)[tid];
        sW3[tid] = reinterpret_cast<const float4*>(W3)[tid];
    }
    if (tid == 0) sb3 = b3[0];
    __syncthreads();

    int gtid = blockIdx.x * 128 + tid;
    int row = gtid >> 1, half = gtid & 1;
    if (row >= B) return;
    unsigned pm = 3u << ((tid & 31) & 30);

    float x[56];
    if (half == 0) {
        const float4* pu = reinterpret_cast<const float4*>(emb_user) + uid[row] * 4;
        const float4* pmv = reinterpret_cast<const float4*>(emb_movie) + mid[row] * 4;
        const float4* py = reinterpret_cast<const float4*>(emb_year) + yr[row] * 4;
        #pragma unroll
        for (int q = 0; q < 4; q++) { float4 v = pu[q];
            x[q*4+0]=v.x; x[q*4+1]=v.y; x[q*4+2]=v.z; x[q*4+3]=v.w; }
        #pragma unroll
        for (int q = 0; q < 4; q++) { float4 v = pmv[q];
            x[16+q*4+0]=v.x; x[16+q*4+1]=v.y; x[16+q*4+2]=v.z; x[16+q*4+3]=v.w; }
        #pragma unroll
        for (int q = 0; q < 4; q++) { float4 v = py[q];
            x[32+q*4+0]=v.x; x[32+q*4+1]=v.y; x[32+q*4+2]=v.z; x[32+q*4+3]=v.w; }
        const float4* pp = reinterpret_cast<const float4*>(g_pooled + row * 64);
        #pragma unroll
        for (int q = 0; q < 2; q++) {
            float4 v = pp[q]; int t0 = q * 4;
            x[48+t0+0] = fa(fm(fm(__fadd_rn(v.x, -sMu[t0+0]), sR[t0+0]), sG[t0+0]), sBt[t0+0]);
            x[48+t0+1] = fa(fm(fm(__fadd_rn(v.y, -sMu[t0+1]), sR[t0+1]), sG[t0+1]), sBt[t0+1]);
            x[48+t0+2] = fa(fm(fm(__fadd_rn(v.z, -sMu[t0+2]), sR[t0+2]), sG[t0+2]), sBt[t0+2]);
            x[48+t0+3] = fa(fm(fm(__fadd_rn(v.w, -sMu[t0+3]), sR[t0+3]), sG[t0+3]), sBt[t0+3]);
        }
    } else {
        const float4* pp = reinterpret_cast<const float4*>(g_pooled + row * 64);
        #pragma unroll
        for (int q = 0; q < 14; q++) {
            float4 v = pp[2 + q]; int t0 = 8 + q * 4;
            x[q*4+0] = fa(fm(fm(__fadd_rn(v.x, -sMu[t0+0]), sR[t0+0]), sG[t0+0]), sBt[t0+0]);
            x[q*4+1] = fa(fm(fm(__fadd_rn(v.y, -sMu[t0+1]), sR[t0+1]), sG[t0+1]), sBt[t0+1]);
            x[q*4+2] = fa(fm(fm(__fadd_rn(v.z, -sMu[t0+2]), sR[t0+2]), sG[t0+2]), sBt[t0+2]);
            x[q*4+3] = fa(fm(fm(__fadd_rn(v.w, -sMu[t0+3]), sR[t0+3]), sG[t0+3]), sBt[t0+3]);
        }
    }

    float4 acc[4];
    #pragma unroll
    for (int kk = 0; kk < 4; kk++) acc[kk] = sb2[half * 4 + kk];

    #pragma unroll 2
    for (int j = 0; j < 64; j++) {
        float t0 = 0.f, t1 = 0.f, t2 = 0.f, t3 = 0.f;
        const float4* wrow = sW1t + j * 28 + half * 14;
        #pragma unroll
        for (int ii = 0; ii < 14; ii++) {
            float4 w = wrow[ii];
            t0 = fmaf(x[ii*4+0], w.x, t0);
            t1 = fmaf(x[ii*4+1], w.y, t1);
            t2 = fmaf(x[ii*4+2], w.z, t2);
            t3 = fmaf(x[ii*4+3], w.w, t3);
        }
        float s = (t0 + t1) + (t2 + t3);
        float o = __shfl_xor_sync(pm, s, 1);
        float slo = half ? o : s;
        float shi = half ? s : o;
        float t = fmaxf(sb1[j] + (slo + shi), 0.f);
        const float4* w2row = sW2 + j * 8 + half * 4;
        #pragma unroll
        for (int kk = 0; kk < 4; kk++) {
            float4 w = w2row[kk];
            acc[kk].x = fmaf(t, w.x, acc[kk].x);
            acc[kk].y = fmaf(t, w.y, acc[kk].y);
            acc[kk].z = fmaf(t, w.z, acc[kk].z);
            acc[kk].w = fmaf(t, w.w, acc[kk].w);
        }
    }

    float zh = 0.f;
    #pragma unroll
    for (int kk = 0; kk < 4; kk++) {
        float4 w = sW3[half * 4 + kk];
        zh += fmaxf(acc[kk].x, 0.f) * w.x + fmaxf(acc[kk].y, 0.f) * w.y
            + fmaxf(acc[kk].z, 0.f) * w.z + fmaxf(acc[kk].w, 0.f) * w.w;
    }
    float oz = __shfl_xor_sync(pm, zh, 1);
    if (half == 0) {
        float z = sb3 + zh + oz;
        out[row] = 1.f / (1.f + expf(-z));
    }
}

// ---------------------------------------------------------------------------
extern "C" void kernel_launch(void* const* d_in, const int* in_sizes, int n_in,
                              void* d_out, int out_size)
{
    const int* user_id  = (const int*)d_in[0];
    const int* movie_id = (const int*)d_in[1];
    const int* year     = (const int*)d_in[2];
    const int* ug       = (const int*)d_in[3];
    const int* urbv     = (const int*)d_in[4];
    const int* mg       = (const int*)d_in[5];
    const int* mt       = (const int*)d_in[6];
    const int* ug_c     = (const int*)d_in[7];
    const int* urb_c    = (const int*)d_in[8];
    const int* mg_c     = (const int*)d_in[9];
    const int* mt_c     = (const int*)d_in[10];
    const float* emb_user  = (const float*)d_in[11];
    const float* emb_movie = (const float*)d_in[12];
    const float* emb_tag   = (const float*)d_in[13];
    const float* emb_genre = (const float*)d_in[14];
    const float* emb_year  = (const float*)d_in[15];
    const float* at_movie  = (const float*)d_in[16];
    // d_in[17] = at_tagId   (unused by korder)
    // d_in[18] = at_genreId (unused by sum/max)
    const float* gamma = (const float*)d_in[19];
    const float* beta  = (const float*)d_in[20];
    const float* W1 = (const float*)d_in[21];
    const float* b1 = (const float*)d_in[22];
    const float* W2 = (const float*)d_in[23];
    const float* b2 = (const float*)d_in[24];
    const float* W3 = (const float*)d_in[25];
    const float* b3 = (const float*)d_in[26];
    int B = in_sizes[0];

    dim3 pgrid((4 * B + 127) / 128, 4);   // f1/f3 use 4 threads/row
    pool8_kernel<<<pgrid, 128>>>(
        ug, urbv, mg, mt, ug_c, urb_c, mg_c, mt_c,
        emb_movie, emb_tag, emb_genre, at_movie, B);
    stats_kernel<<<256, 64>>>(B);
    bn_kernel<<<1, 128>>>(W1, B);
    mlp3_kernel<<<(2 * B + 127) / 128, 128>>>(
        user_id, movie_id, year, emb_user, emb_movie, emb_year,
        gamma, beta, b1, W2, b2, W3, b3, (float*)d_out, B);
}